// round 15
// baseline (speedup 1.0000x reference)
#include <cuda_runtime.h>
#include <math.h>
#include <stdint.h>

#define BATCH 256
#define GHH 100
#define GWW 100
#define CH 32
#define TPAST 20
#define TFUT 30
#define NPIX (GHH * GWW)

// Ping-pong scratch for the conv stack (sanctioned __device__ global scratch).
// Pair layout (intermediate layers): per pixel 32 words = [16 hi][16 lo] bf16x2.
__device__ __align__(128) float g_bufA[(size_t)BATCH*NPIX*CH];
__device__ __align__(128) float g_bufB[(size_t)BATCH*NPIX*CH];
// Collapsed MLP: W = mlp_w2 @ mlp_w1 (4x32), wb = mlp_w2 @ mlp_b1 + mlp_b2.
__device__ float g_W[128];
__device__ float g_wb[4];

// ---------------------------------------------------------------------------
// convF: 2x2 conv (32ch->32ch) as warp-level mma.sync bf16 m16n8k16 GEMM with
// 3-term compensation (D = Ah*Bh + Al*Bh + Ah*Bl).
// R15: warp-split for occupancy — 448 threads/CTA, each warp owns ONE m16
// tile (16 pixels x 32 oc). Registers/thread ~65 -> __launch_bounds__(448,2)
// gives 28 warps/SM (vs 21) and halves the per-warp MMA critical path.
// mode bits: 1 = fuse conv0 (layer 1), 2 = pair input, 4 = pair output.
// ---------------------------------------------------------------------------
#define PIXB 224
#define NTHR 448
#define APITCH 20                 // uint32 words per pixel (16 pairs + pad)
#define BPITCH 68                 // uint32 words per out-channel (64 pairs + pad)
#define NSTRIP 326                // data rows 0..324, ZROW = 325
#define ZROW 325
#define NLID 427                  // lidar strip pixels staged for layer 1
#define OFF_AH 0
#define OFF_AL (NSTRIP * APITCH)
#define OFF_BH (2 * NSTRIP * APITCH)
#define OFF_BL (OFF_BH + 32 * BPITCH)
#define OFF_BI (OFF_BL + 32 * BPITCH)
#define OFF_LID (OFF_BI + 32)
#define CM_WORDS (OFF_LID + NLID * 2 + 2)
#define CM_SMEM (CM_WORDS * 4)
#define ALOFS ((OFF_AL - OFF_AH) * 4)   // byte offset hi->lo plane (A)
#define BLOFS ((OFF_BL - OFF_BH) * 4)   // byte offset hi->lo plane (B)

#define MMA_BF16(C, A0, A1, A2, A3, B0, B1)                                  \
    asm volatile("mma.sync.aligned.m16n8k16.row.col.f32.bf16.bf16.f32 "      \
                 "{%0,%1,%2,%3}, {%4,%5,%6,%7}, {%8,%9}, {%0,%1,%2,%3};"     \
                 : "+f"(C[0]), "+f"(C[1]), "+f"(C[2]), "+f"(C[3])            \
                 : "r"(A0), "r"(A1), "r"(A2), "r"(A3), "r"(B0), "r"(B1))

#define LDSM_X4(R, addr)                                                     \
    asm volatile("ldmatrix.sync.aligned.m8n8.x4.shared.b16 "                 \
                 "{%0,%1,%2,%3}, [%4];"                                      \
                 : "=r"((R)[0]), "=r"((R)[1]), "=r"((R)[2]), "=r"((R)[3])    \
                 : "r"(addr))

__device__ __forceinline__ uint32_t bf16x2_of(float lo, float hi) {
    uint32_t r;
    asm("cvt.rn.bf16x2.f32 %0, %1, %2;" : "=r"(r) : "f"(hi), "f"(lo));
    return r;
}
__device__ __forceinline__ float2 bf16x2_to_f2(uint32_t u) {
    float2 r;
    r.x = __uint_as_float(u << 16);
    r.y = __uint_as_float(u & 0xFFFF0000u);
    return r;
}

__global__ void __launch_bounds__(NTHR, 2) convF_kernel(
    const float* __restrict__ w,  const float* __restrict__ bias,
    const float* __restrict__ w0, const float* __restrict__ b0,
    const float* __restrict__ lidar, int srcIsA, int mode) {
    extern __shared__ uint32_t smu[];
    const float* in   = srcIsA ? g_bufA : g_bufB;
    float*       outp = srcIsA ? g_bufB : g_bufA;

    int tid = threadIdx.x;
    int b   = blockIdx.y;
    int p0  = blockIdx.x * PIXB;
    uint32_t sbase = (uint32_t)__cvta_generic_to_shared(smu);

    // ---- phase 1: issue async gmem->smem copies FIRST ----
    if (mode & 1) {
        const float* lb = lidar + (size_t)b * NPIX * 2;
        for (int i = tid; i < NLID; i += NTHR) {
            int gp = p0 + i;
            uint32_t daddr = sbase + (uint32_t)(OFF_LID + 2 * i) * 4u;
            if (gp < NPIX) {
                asm volatile("cp.async.ca.shared.global [%0], [%1], 8;"
                             :: "r"(daddr), "l"(lb + (size_t)gp * 2));
            } else {
                smu[OFF_LID + 2 * i]     = 0u;
                smu[OFF_LID + 2 * i + 1] = 0u;
            }
        }
    } else {
        const uint4* src = reinterpret_cast<const uint4*>(in) + (size_t)b * NPIX * 8;
        for (int i = tid; i < NSTRIP * 8; i += NTHR) {
            int pix = i >> 3, c = i & 7;
            int gp = p0 + pix;
            uint32_t dw = (uint32_t)(((c >> 2) ? OFF_AL : OFF_AH)
                                     + pix * APITCH + (c & 3) * 4);
            if (pix < ZROW && gp < NPIX) {
                const uint4* gsrc = src + (size_t)gp * 8 + c;
                asm volatile("cp.async.cg.shared.global [%0], [%1], 16;"
                             :: "r"(sbase + dw * 4u), "l"(gsrc));
            } else {
                *reinterpret_cast<uint4*>(&smu[dw]) = make_uint4(0u, 0u, 0u, 0u);
            }
        }
    }
    asm volatile("cp.async.commit_group;" ::: "memory");

    // ---- phase 2 (overlapped with copies): weights -> bf16x2 hi/lo pairs ----
    for (int i = tid; i < 2048; i += NTHR) {
        int n = i & 31, j = i >> 5;
        float v0 = w[(2 * j) * 32 + n];
        float v1 = w[(2 * j + 1) * 32 + n];
        uint32_t h = bf16x2_of(v0, v1);
        float2 hf = bf16x2_to_f2(h);
        uint32_t l = bf16x2_of(v0 - hf.x, v1 - hf.y);
        smu[OFF_BH + n * BPITCH + j] = h;
        smu[OFF_BL + n * BPITCH + j] = l;
    }
    if (tid < 32) ((float*)smu)[OFF_BI + tid] = bias[tid];

    asm volatile("cp.async.wait_group 0;" ::: "memory");
    __syncthreads();

    if (mode & 1) {
        // ---- layer-1: conv0(lidar)+relu from the staged smem strip ----
        int sub = tid & 7;
        float wc[8][4], bc[4];
#pragma unroll
        for (int q = 0; q < 4; q++) bc[q] = b0[sub * 4 + q];
#pragma unroll
        for (int k = 0; k < 8; k++)
#pragma unroll
            for (int q = 0; q < 4; q++) wc[k][q] = w0[k * 32 + sub * 4 + q];

        const float* sl = (const float*)&smu[OFF_LID];
        for (int u = tid; u < NSTRIP * 8; u += NTHR) {
            int pix = u >> 3;
            int gp = p0 + pix;
            uint32_t h0 = 0, h1 = 0, l0 = 0, l1 = 0;
            if (pix < ZROW && gp < NPIX) {
                int y = gp / GWW, x = gp % GWW;
                bool xe = (x == GWW - 1), ye = (y == GHH - 1);
                float a[8];
#pragma unroll
                for (int dy = 0; dy < 2; dy++)
#pragma unroll
                    for (int dx = 0; dx < 2; dx++) {
                        bool ok = !(dy && ye) && !(dx && xe);
                        const float* ip = sl + (pix + dy * GWW + dx) * 2;
                        a[(dy * 2 + dx) * 2 + 0] = ok ? ip[0] : 0.f;
                        a[(dy * 2 + dx) * 2 + 1] = ok ? ip[1] : 0.f;
                    }
                float v[4];
#pragma unroll
                for (int q = 0; q < 4; q++) {
                    float s = bc[q];
#pragma unroll
                    for (int k = 0; k < 8; k++) s += a[k] * wc[k][q];
                    v[q] = fmaxf(s, 0.f);
                }
                h0 = bf16x2_of(v[0], v[1]);
                h1 = bf16x2_of(v[2], v[3]);
                float2 f0 = bf16x2_to_f2(h0), f1 = bf16x2_to_f2(h1);
                l0 = bf16x2_of(v[0] - f0.x, v[1] - f0.y);
                l1 = bf16x2_of(v[2] - f1.x, v[3] - f1.y);
            }
            int j = sub * 2;
            smu[OFF_AH + pix * APITCH + j]     = h0;
            smu[OFF_AH + pix * APITCH + j + 1] = h1;
            smu[OFF_AL + pix * APITCH + j]     = l0;
            smu[OFF_AL + pix * APITCH + j + 1] = l1;
        }
        __syncthreads();
    }

    int lane = tid & 31, wid = tid >> 5;            // wid 0..13
    int g = lane >> 2, tg = lane & 3;
    int m_warp = wid * 16;                          // ONE m16 tile per warp

    // ---- per-lane ldmatrix row addresses ----
    int row16  = ((lane >> 3) & 1) * 8 + (lane & 7);
    int khalfA = (lane >> 4) & 1;
    uint32_t aaddr[4];                              // [tap], hi plane, bytes
    {
        int pix = m_warp + row16;
        bool wrap = (((p0 + pix) % GWW) == (GWW - 1));
#pragma unroll
        for (int tap = 0; tap < 4; tap++) {
            int rr = pix + (tap >> 1) * GWW + (tap & 1);
            int rowpix = ((tap & 1) && wrap) ? ZROW : rr;
            aaddr[tap] = sbase + (uint32_t)(rowpix * APITCH + khalfA * 4) * 4u;
        }
    }
    int ntp  = (lane >> 4) & 1;
    int matk = (lane >> 3) & 1;
    int nrow = lane & 7;
    uint32_t baddr[2];                              // [pair], hi plane, bytes
#pragma unroll
    for (int p = 0; p < 2; p++)
        baddr[p] = sbase + (uint32_t)(OFF_BH + ((2 * p + ntp) * 8 + nrow) * BPITCH
                                      + matk * 4) * 4u;

    float acc[4][4];
#pragma unroll
    for (int nt = 0; nt < 4; nt++)
#pragma unroll
        for (int q = 0; q < 4; q++) acc[nt][q] = 0.f;

#pragma unroll
    for (int s = 0; s < 8; s++) {                   // K = 128 = 8 x k16
        int tap = s >> 1, sh = s & 1;
        uint32_t ka = (uint32_t)(sh * 8) * 4u;
        uint32_t kb = (uint32_t)(tap * 16 + sh * 8) * 4u;

        uint32_t AH[4], AL[4];
        {
            uint32_t ad = aaddr[tap] + ka;
            LDSM_X4(AH, ad);
            LDSM_X4(AL, ad + ALOFS);
        }
        uint32_t BH[2][4], BL[2][4];
#pragma unroll
        for (int p = 0; p < 2; p++) {
            uint32_t bd = baddr[p] + kb;
            LDSM_X4(BH[p], bd);
            LDSM_X4(BL[p], bd + BLOFS);
        }

#pragma unroll
        for (int nt = 0; nt < 4; nt++) {
            int p = nt >> 1, q2 = (nt & 1) * 2;
            uint32_t bh0 = BH[p][q2], bh1 = BH[p][q2 + 1];
            uint32_t bl0 = BL[p][q2], bl1 = BL[p][q2 + 1];
            MMA_BF16(acc[nt], AH[0], AH[1], AH[2], AH[3], bh0, bh1);
            MMA_BF16(acc[nt], AL[0], AL[1], AL[2], AL[3], bh0, bh1);
            MMA_BF16(acc[nt], AH[0], AH[1], AH[2], AH[3], bl0, bl1);
        }
    }

    // ---- epilogue: bias + relu ----
    const float* sbias = ((const float*)smu) + OFF_BI;
    if (mode & 4) {
        // pair output: per pixel [16 hi][16 lo] words
#pragma unroll
        for (int half = 0; half < 2; half++) {
            int pp = p0 + m_warp + half * 8 + g;
            if (pp < NPIX) {
                uint32_t* op = reinterpret_cast<uint32_t*>(outp)
                               + (size_t)(b * NPIX + pp) * 32;
#pragma unroll
                for (int nt = 0; nt < 4; nt++) {
                    int col = nt * 8 + tg * 2;
                    float vx = fmaxf(acc[nt][half * 2 + 0] + sbias[col],     0.f);
                    float vy = fmaxf(acc[nt][half * 2 + 1] + sbias[col + 1], 0.f);
                    uint32_t h = bf16x2_of(vx, vy);
                    float2 hf = bf16x2_to_f2(h);
                    uint32_t l = bf16x2_of(vx - hf.x, vy - hf.y);
                    op[col >> 1]        = h;
                    op[16 + (col >> 1)] = l;
                }
            }
        }
    } else {
        // fp32 output (final layer; consumed by seq_kernel)
#pragma unroll
        for (int half = 0; half < 2; half++) {
            int pp = p0 + m_warp + half * 8 + g;
            if (pp < NPIX) {
                float* op = outp + ((size_t)b * NPIX + pp) * 32;
#pragma unroll
                for (int nt = 0; nt < 4; nt++) {
                    int col = nt * 8 + tg * 2;
                    float2 v;
                    v.x = fmaxf(acc[nt][half * 2 + 0] + sbias[col],     0.f);
                    v.y = fmaxf(acc[nt][half * 2 + 1] + sbias[col + 1], 0.f);
                    *reinterpret_cast<float2*>(op + col) = v;
                }
            }
        }
    }
}

// ---------------------------------------------------------------------------
// mlp_collapse: W(4x32) = w2(4x512) @ w1(512x32); wb = w2 @ b1 + b2.
// ---------------------------------------------------------------------------
__global__ void __launch_bounds__(128) mlp_collapse_kernel(
    const float* __restrict__ w1, const float* __restrict__ b1,
    const float* __restrict__ w2, const float* __restrict__ b2) {
    int tid = threadIdx.x;
    int o = tid >> 5, i = tid & 31;
    const float* w2r = w2 + o * 512;
    float s = 0.f;
#pragma unroll 8
    for (int k = 0; k < 512; k++) s += w2r[k] * w1[k * 32 + i];
    g_W[tid] = s;
    if (tid < 4) {
        const float* wr = w2 + tid * 512;
        float sb = 0.f;
#pragma unroll 8
        for (int k = 0; k < 512; k++) sb += wr[k] * b1[k];
        g_wb[tid] = sb + b2[tid];
    }
}

// ---------------------------------------------------------------------------
// seq: warp-per-batch-row GRU encoder + autoregressive decoder (R10 design).
// ---------------------------------------------------------------------------
#define FULLM 0xffffffffu
__device__ __forceinline__ float sigmoidf_(float v) { return 1.f / (1.f + expf(-v)); }
__device__ __forceinline__ float softplusf_(float v) {
    return fmaxf(v, 0.f) + log1pf(expf(-fabsf(v)));
}

__global__ void __launch_bounds__(32) seq_kernel(
    const float* __restrict__ z,    const float* __restrict__ past,
    const float* __restrict__ ewih, const float* __restrict__ ewhh,
    const float* __restrict__ ebih, const float* __restrict__ ebhh,
    const float* __restrict__ dwih, const float* __restrict__ dwhh,
    const float* __restrict__ dbih, const float* __restrict__ dbhh,
    float* __restrict__ out) {
    int b = blockIdx.x, i = threadIdx.x;

    __shared__ __align__(16) float s_ewhh[96 * 36];
    __shared__ __align__(16) float s_dwhh[96 * 36];
    __shared__ __align__(16) float s_dwih[96 * 36];   // [0,1]=y1 wts, [4..35]=interp wts
    __shared__ float s_eih[192];
    __shared__ float s_ebih[96], s_ebhh[96], s_dbih[96], s_dbhh[96];
    __shared__ float s_W[128], s_wb[4];

    for (int u = i; u < 3072; u += 32) {
        int r = u >> 5, c = u & 31;
        s_ewhh[r * 36 + c] = ewhh[u];
        s_dwhh[r * 36 + c] = dwhh[u];
    }
    for (int u = i; u < 96 * 34; u += 32) {
        int r = u / 34, c = u % 34;
        s_dwih[r * 36 + (c < 2 ? c : c + 2)] = dwih[u];
    }
    for (int u = i; u < 192; u += 32) s_eih[u] = ewih[u];
    for (int u = i; u < 96; u += 32) {
        s_ebih[u] = ebih[u]; s_ebhh[u] = ebhh[u];
        s_dbih[u] = dbih[u]; s_dbhh[u] = dbhh[u];
    }
    for (int u = i; u < 128; u += 32) s_W[u] = g_W[u];
    if (i < 4) s_wb[i] = g_wb[i];
    __syncwarp();

    float hi = 0.f;
    float harr[32];
#pragma unroll
    for (int k = 0; k < 32; k++) harr[k] = 0.f;

    const float* pb = past + (size_t)b * TPAST * 2;
    for (int t = 0; t < TPAST; t++) {
        float x0 = pb[2 * t], x1 = pb[2 * t + 1];
        float g0 = s_ebih[i]      + x0 * s_eih[2 * i]            + x1 * s_eih[2 * i + 1];
        float g1 = s_ebih[32 + i] + x0 * s_eih[2 * (32 + i)]     + x1 * s_eih[2 * (32 + i) + 1];
        float g2 = s_ebih[64 + i] + x0 * s_eih[2 * (64 + i)]     + x1 * s_eih[2 * (64 + i) + 1];
        float h0 = s_ebhh[i], h1 = s_ebhh[32 + i], h2 = s_ebhh[64 + i];
        const float4* w0p = (const float4*)&s_ewhh[i * 36];
        const float4* w1p = (const float4*)&s_ewhh[(32 + i) * 36];
        const float4* w2p = (const float4*)&s_ewhh[(64 + i) * 36];
#pragma unroll
        for (int q = 0; q < 8; q++) {
            float4 a0 = w0p[q], a1 = w1p[q], a2 = w2p[q];
            float k0 = harr[4 * q], k1 = harr[4 * q + 1], k2 = harr[4 * q + 2], k3 = harr[4 * q + 3];
            h0 += k0 * a0.x + k1 * a0.y + k2 * a0.z + k3 * a0.w;
            h1 += k0 * a1.x + k1 * a1.y + k2 * a1.z + k3 * a1.w;
            h2 += k0 * a2.x + k1 * a2.y + k2 * a2.z + k3 * a2.w;
        }
        float rg = sigmoidf_(g0 + h0);
        float zg = sigmoidf_(g1 + h1);
        float nn = tanhf(g2 + rg * h2);
        hi = (1.f - zg) * nn + zg * hi;
#pragma unroll
        for (int k = 0; k < 32; k++) harr[k] = __shfl_sync(FULLM, hi, k);
    }

    float y1x = pb[2 * 19], y1y = pb[2 * 19 + 1];
    float y2x = pb[2 * 18], y2y = pb[2 * 18 + 1];
    float prod0 = 1.f, prod1 = 1.f;
    const float* ctx = g_bufB + (size_t)b * NPIX * 32;
    const float* zb = z + (size_t)b * TFUT * 2;

    for (int t = 0; t < TFUT; t++) {
        float fyf = fminf(fmaxf(floorf(y1x), 0.f), (float)(GHH - 2));
        float fxf = fminf(fmaxf(floorf(y1y), 0.f), (float)(GWW - 2));
        float ay = fminf(fmaxf(y1x - fyf, 0.f), 1.f);
        float ax = fminf(fmaxf(y1y - fxf, 0.f), 1.f);
        int fy = (int)fyf, fx = (int)fxf;
        const float* gb = ctx + ((size_t)fy * GWW + fx) * 32 + i;
        float tl = gb[0], tr = gb[32], bl = gb[GWW * 32], br = gb[GWW * 32 + 32];
        float top = tl + ax * (tr - tl);
        float bot = bl + ax * (br - bl);
        float xi = top + ay * (bot - top);
        float xarr[32];
#pragma unroll
        for (int k = 0; k < 32; k++) xarr[k] = __shfl_sync(FULLM, xi, k);

        float g0 = s_dbih[i]      + y1x * s_dwih[i * 36]            + y1y * s_dwih[i * 36 + 1];
        float g1 = s_dbih[32 + i] + y1x * s_dwih[(32 + i) * 36]     + y1y * s_dwih[(32 + i) * 36 + 1];
        float g2 = s_dbih[64 + i] + y1x * s_dwih[(64 + i) * 36]     + y1y * s_dwih[(64 + i) * 36 + 1];
        float h0 = s_dbhh[i], h1 = s_dbhh[32 + i], h2 = s_dbhh[64 + i];
        {
            const float4* xi0 = (const float4*)&s_dwih[i * 36 + 4];
            const float4* xi1 = (const float4*)&s_dwih[(32 + i) * 36 + 4];
            const float4* xi2 = (const float4*)&s_dwih[(64 + i) * 36 + 4];
            const float4* w0p = (const float4*)&s_dwhh[i * 36];
            const float4* w1p = (const float4*)&s_dwhh[(32 + i) * 36];
            const float4* w2p = (const float4*)&s_dwhh[(64 + i) * 36];
#pragma unroll
            for (int q = 0; q < 8; q++) {
                float4 a0 = xi0[q], a1 = xi1[q], a2 = xi2[q];
                float k0 = xarr[4 * q], k1 = xarr[4 * q + 1], k2 = xarr[4 * q + 2], k3 = xarr[4 * q + 3];
                g0 += k0 * a0.x + k1 * a0.y + k2 * a0.z + k3 * a0.w;
                g1 += k0 * a1.x + k1 * a1.y + k2 * a1.z + k3 * a1.w;
                g2 += k0 * a2.x + k1 * a2.y + k2 * a2.z + k3 * a2.w;
                float4 c0 = w0p[q], c1 = w1p[q], c2 = w2p[q];
                float m0 = harr[4 * q], m1 = harr[4 * q + 1], m2 = harr[4 * q + 2], m3 = harr[4 * q + 3];
                h0 += m0 * c0.x + m1 * c0.y + m2 * c0.z + m3 * c0.w;
                h1 += m0 * c1.x + m1 * c1.y + m2 * c1.z + m3 * c1.w;
                h2 += m0 * c2.x + m1 * c2.y + m2 * c2.z + m3 * c2.w;
            }
        }
        float rg = sigmoidf_(g0 + h0);
        float zg = sigmoidf_(g1 + h1);
        float nn = tanhf(g2 + rg * h2);
        hi = (1.f - zg) * nn + zg * hi;
#pragma unroll
        for (int k = 0; k < 32; k++) harr[k] = __shfl_sync(FULLM, hi, k);

        float p0 = s_W[i] * hi;
        float p1 = s_W[32 + i] * hi;
        float p2 = s_W[64 + i] * hi;
        float p3 = s_W[96 + i] * hi;
#pragma unroll
        for (int off = 16; off; off >>= 1) {
            p0 += __shfl_xor_sync(FULLM, p0, off);
            p1 += __shfl_xor_sync(FULLM, p1, off);
            p2 += __shfl_xor_sync(FULLM, p2, off);
            p3 += __shfl_xor_sync(FULLM, p3, off);
        }
        float loc0 = p0 + s_wb[0], loc1 = p1 + s_wb[1];
        float s0 = softplusf_(p2 + s_wb[2]);
        float s1 = softplusf_(p3 + s_wb[3]);
        float zt0 = zb[2 * t], zt1 = zb[2 * t + 1];
        float ynx = 2.f * y1x - y2x + loc0 + s0 * zt0;
        float yny = 2.f * y1y - y2y + loc1 + s1 * zt1;
        if (i == 0) {
            out[((size_t)b * TFUT + t) * 2]     = ynx;
            out[((size_t)b * TFUT + t) * 2 + 1] = yny;
        }
        prod0 *= s0; prod1 *= s1;
        y2x = y1x; y2y = y1y;
        y1x = ynx; y1y = yny;
    }
    if (i == 0)
        out[(size_t)BATCH * TFUT * 2 + b] = logf(fabsf(prod0)) + logf(fabsf(prod1));
}

// ---------------------------------------------------------------------------
extern "C" void kernel_launch(void* const* d_in, const int* in_sizes, int n_in,
                              void* d_out, int out_size) {
    const float* z    = (const float*)d_in[0];
    const float* past = (const float*)d_in[1];
    const float* lidar= (const float*)d_in[2];
    const float* c0w  = (const float*)d_in[3];
    const float* c0b  = (const float*)d_in[4];
    const float* c1w  = (const float*)d_in[5];
    const float* c1b  = (const float*)d_in[6];
    const float* c2w  = (const float*)d_in[7];
    const float* c2b  = (const float*)d_in[8];
    const float* c3w  = (const float*)d_in[9];
    const float* c3b  = (const float*)d_in[10];
    const float* ewih = (const float*)d_in[11];
    const float* ewhh = (const float*)d_in[12];
    const float* ebih = (const float*)d_in[13];
    const float* ebhh = (const float*)d_in[14];
    const float* dwih = (const float*)d_in[15];
    const float* dwhh = (const float*)d_in[16];
    const float* dbih = (const float*)d_in[17];
    const float* dbhh = (const float*)d_in[18];
    const float* w1   = (const float*)d_in[19];
    const float* b1   = (const float*)d_in[20];
    const float* w2   = (const float*)d_in[21];
    const float* b2   = (const float*)d_in[22];
    float* out = (float*)d_out;

    cudaFuncSetAttribute(convF_kernel, cudaFuncAttributeMaxDynamicSharedMemorySize,
                         CM_SMEM);

    mlp_collapse_kernel<<<1, 128>>>(w1, b1, w2, b2);

    dim3 cg((NPIX + PIXB - 1) / PIXB, BATCH);
    // layer 1: conv0 fused, pair output          -> g_bufB (pairs)
    convF_kernel<<<cg, NTHR, CM_SMEM>>>(c1w, c1b, c0w, c0b, lidar, 1, 1 | 4);
    // layer 2: pair input, pair output           g_bufB -> g_bufA (pairs)
    convF_kernel<<<cg, NTHR, CM_SMEM>>>(c2w, c2b, c0w, c0b, lidar, 0, 2 | 4);
    // layer 3: pair input, fp32 output           g_bufA -> g_bufB (fp32 ctx)
    convF_kernel<<<cg, NTHR, CM_SMEM>>>(c3w, c3b, c0w, c0b, lidar, 1, 2);

    seq_kernel<<<BATCH, 32>>>(z, past, ewih, ewhh, ebih, ebhh,
                              dwih, dwhh, dbih, dbhh, out);
}

// round 16
// speedup vs baseline: 1.0638x; 1.0638x over previous
#include <cuda_runtime.h>
#include <math.h>
#include <stdint.h>

#define BATCH 256
#define GHH 100
#define GWW 100
#define CH 32
#define TPAST 20
#define TFUT 30
#define NPIX (GHH * GWW)

// Ping-pong scratch for the conv stack (sanctioned __device__ global scratch).
// Pair layout (intermediate layers): per pixel 32 words = [16 hi][16 lo] bf16x2.
__device__ __align__(128) float g_bufA[(size_t)BATCH*NPIX*CH];
__device__ __align__(128) float g_bufB[(size_t)BATCH*NPIX*CH];
// Collapsed MLP: W = mlp_w2 @ mlp_w1 (4x32), wb = mlp_w2 @ mlp_b1 + mlp_b2.
__device__ float g_W[128];
__device__ float g_wb[4];

// ---------------------------------------------------------------------------
// convF: 2x2 conv (32ch->32ch) as warp-level mma.sync bf16 m16n8k16 GEMM with
// 3-term compensation (D = Ah*Bh + Al*Bh + Ah*Bl).  (R14 config — reverted
// from the R15 warp-split, which raised per-SM shared traffic and regressed.)
// mode bits: 1 = fuse conv0 (layer 1), 2 = pair input, 4 = pair output.
// ---------------------------------------------------------------------------
#define PIXB 224
#define NTHR 224
#define APITCH 20                 // uint32 words per pixel (16 pairs + pad)
#define BPITCH 68                 // uint32 words per out-channel (64 pairs + pad)
#define NSTRIP 326                // data rows 0..324, ZROW = 325
#define ZROW 325
#define NLID 427                  // lidar strip pixels staged for layer 1
#define OFF_AH 0
#define OFF_AL (NSTRIP * APITCH)
#define OFF_BH (2 * NSTRIP * APITCH)
#define OFF_BL (OFF_BH + 32 * BPITCH)
#define OFF_BI (OFF_BL + 32 * BPITCH)
#define OFF_LID (OFF_BI + 32)
#define CM_WORDS (OFF_LID + NLID * 2 + 2)
#define CM_SMEM (CM_WORDS * 4)
#define ALOFS ((OFF_AL - OFF_AH) * 4)   // byte offset hi->lo plane (A)
#define BLOFS ((OFF_BL - OFF_BH) * 4)   // byte offset hi->lo plane (B)

#define MMA_BF16(C, A0, A1, A2, A3, B0, B1)                                  \
    asm volatile("mma.sync.aligned.m16n8k16.row.col.f32.bf16.bf16.f32 "      \
                 "{%0,%1,%2,%3}, {%4,%5,%6,%7}, {%8,%9}, {%0,%1,%2,%3};"     \
                 : "+f"(C[0]), "+f"(C[1]), "+f"(C[2]), "+f"(C[3])            \
                 : "r"(A0), "r"(A1), "r"(A2), "r"(A3), "r"(B0), "r"(B1))

#define LDSM_X4(R, addr)                                                     \
    asm volatile("ldmatrix.sync.aligned.m8n8.x4.shared.b16 "                 \
                 "{%0,%1,%2,%3}, [%4];"                                      \
                 : "=r"((R)[0]), "=r"((R)[1]), "=r"((R)[2]), "=r"((R)[3])    \
                 : "r"(addr))

__device__ __forceinline__ uint32_t bf16x2_of(float lo, float hi) {
    uint32_t r;
    asm("cvt.rn.bf16x2.f32 %0, %1, %2;" : "=r"(r) : "f"(hi), "f"(lo));
    return r;
}
__device__ __forceinline__ float2 bf16x2_to_f2(uint32_t u) {
    float2 r;
    r.x = __uint_as_float(u << 16);
    r.y = __uint_as_float(u & 0xFFFF0000u);
    return r;
}

__global__ void __launch_bounds__(NTHR, 3) convF_kernel(
    const float* __restrict__ w,  const float* __restrict__ bias,
    const float* __restrict__ w0, const float* __restrict__ b0,
    const float* __restrict__ lidar, int srcIsA, int mode) {
    extern __shared__ uint32_t smu[];
    const float* in   = srcIsA ? g_bufA : g_bufB;
    float*       outp = srcIsA ? g_bufB : g_bufA;

    int tid = threadIdx.x;
    int b   = blockIdx.y;
    int p0  = blockIdx.x * PIXB;
    uint32_t sbase = (uint32_t)__cvta_generic_to_shared(smu);

    // ---- phase 1: issue async gmem->smem copies FIRST ----
    if (mode & 1) {
        const float* lb = lidar + (size_t)b * NPIX * 2;
        for (int i = tid; i < NLID; i += NTHR) {
            int gp = p0 + i;
            uint32_t daddr = sbase + (uint32_t)(OFF_LID + 2 * i) * 4u;
            if (gp < NPIX) {
                asm volatile("cp.async.ca.shared.global [%0], [%1], 8;"
                             :: "r"(daddr), "l"(lb + (size_t)gp * 2));
            } else {
                smu[OFF_LID + 2 * i]     = 0u;
                smu[OFF_LID + 2 * i + 1] = 0u;
            }
        }
    } else {
        const uint4* src = reinterpret_cast<const uint4*>(in) + (size_t)b * NPIX * 8;
        for (int i = tid; i < NSTRIP * 8; i += NTHR) {
            int pix = i >> 3, c = i & 7;
            int gp = p0 + pix;
            uint32_t dw = (uint32_t)(((c >> 2) ? OFF_AL : OFF_AH)
                                     + pix * APITCH + (c & 3) * 4);
            if (pix < ZROW && gp < NPIX) {
                const uint4* gsrc = src + (size_t)gp * 8 + c;
                asm volatile("cp.async.cg.shared.global [%0], [%1], 16;"
                             :: "r"(sbase + dw * 4u), "l"(gsrc));
            } else {
                *reinterpret_cast<uint4*>(&smu[dw]) = make_uint4(0u, 0u, 0u, 0u);
            }
        }
    }
    asm volatile("cp.async.commit_group;" ::: "memory");

    // ---- phase 2 (overlapped with copies): weights -> bf16x2 hi/lo pairs ----
    for (int i = tid; i < 2048; i += NTHR) {
        int n = i & 31, j = i >> 5;
        float v0 = w[(2 * j) * 32 + n];
        float v1 = w[(2 * j + 1) * 32 + n];
        uint32_t h = bf16x2_of(v0, v1);
        float2 hf = bf16x2_to_f2(h);
        uint32_t l = bf16x2_of(v0 - hf.x, v1 - hf.y);
        smu[OFF_BH + n * BPITCH + j] = h;
        smu[OFF_BL + n * BPITCH + j] = l;
    }
    if (tid < 32) ((float*)smu)[OFF_BI + tid] = bias[tid];

    asm volatile("cp.async.wait_group 0;" ::: "memory");
    __syncthreads();

    if (mode & 1) {
        // ---- layer-1: conv0(lidar)+relu from the staged smem strip ----
        int sub = tid & 7;
        float wc[8][4], bc[4];
#pragma unroll
        for (int q = 0; q < 4; q++) bc[q] = b0[sub * 4 + q];
#pragma unroll
        for (int k = 0; k < 8; k++)
#pragma unroll
            for (int q = 0; q < 4; q++) wc[k][q] = w0[k * 32 + sub * 4 + q];

        const float* sl = (const float*)&smu[OFF_LID];
        for (int u = tid; u < NSTRIP * 8; u += NTHR) {
            int pix = u >> 3;
            int gp = p0 + pix;
            uint32_t h0 = 0, h1 = 0, l0 = 0, l1 = 0;
            if (pix < ZROW && gp < NPIX) {
                int y = gp / GWW, x = gp % GWW;
                bool xe = (x == GWW - 1), ye = (y == GHH - 1);
                float a[8];
#pragma unroll
                for (int dy = 0; dy < 2; dy++)
#pragma unroll
                    for (int dx = 0; dx < 2; dx++) {
                        bool ok = !(dy && ye) && !(dx && xe);
                        const float* ip = sl + (pix + dy * GWW + dx) * 2;
                        a[(dy * 2 + dx) * 2 + 0] = ok ? ip[0] : 0.f;
                        a[(dy * 2 + dx) * 2 + 1] = ok ? ip[1] : 0.f;
                    }
                float v[4];
#pragma unroll
                for (int q = 0; q < 4; q++) {
                    float s = bc[q];
#pragma unroll
                    for (int k = 0; k < 8; k++) s += a[k] * wc[k][q];
                    v[q] = fmaxf(s, 0.f);
                }
                h0 = bf16x2_of(v[0], v[1]);
                h1 = bf16x2_of(v[2], v[3]);
                float2 f0 = bf16x2_to_f2(h0), f1 = bf16x2_to_f2(h1);
                l0 = bf16x2_of(v[0] - f0.x, v[1] - f0.y);
                l1 = bf16x2_of(v[2] - f1.x, v[3] - f1.y);
            }
            int j = sub * 2;
            smu[OFF_AH + pix * APITCH + j]     = h0;
            smu[OFF_AH + pix * APITCH + j + 1] = h1;
            smu[OFF_AL + pix * APITCH + j]     = l0;
            smu[OFF_AL + pix * APITCH + j + 1] = l1;
        }
        __syncthreads();
    }

    int lane = tid & 31, wid = tid >> 5;            // wid 0..6
    int g = lane >> 2, tg = lane & 3;
    int m_warp = wid * 32;

    // ---- per-lane ldmatrix row addresses ----
    int row16  = ((lane >> 3) & 1) * 8 + (lane & 7);
    int khalfA = (lane >> 4) & 1;
    uint32_t aaddr[2][4];                           // [mt][tap], hi plane, bytes
#pragma unroll
    for (int mt = 0; mt < 2; mt++) {
        int pix = m_warp + mt * 16 + row16;
        bool wrap = (((p0 + pix) % GWW) == (GWW - 1));
#pragma unroll
        for (int tap = 0; tap < 4; tap++) {
            int rr = pix + (tap >> 1) * GWW + (tap & 1);
            int rowpix = ((tap & 1) && wrap) ? ZROW : rr;
            aaddr[mt][tap] = sbase + (uint32_t)(rowpix * APITCH + khalfA * 4) * 4u;
        }
    }
    int ntp  = (lane >> 4) & 1;
    int matk = (lane >> 3) & 1;
    int nrow = lane & 7;
    uint32_t baddr[2];                              // [pair], hi plane, bytes
#pragma unroll
    for (int p = 0; p < 2; p++)
        baddr[p] = sbase + (uint32_t)(OFF_BH + ((2 * p + ntp) * 8 + nrow) * BPITCH
                                      + matk * 4) * 4u;

    float acc[2][4][4];
#pragma unroll
    for (int mt = 0; mt < 2; mt++)
#pragma unroll
        for (int nt = 0; nt < 4; nt++)
#pragma unroll
            for (int q = 0; q < 4; q++) acc[mt][nt][q] = 0.f;

#pragma unroll
    for (int s = 0; s < 8; s++) {                   // K = 128 = 8 x k16
        int tap = s >> 1, sh = s & 1;
        uint32_t ka = (uint32_t)(sh * 8) * 4u;
        uint32_t kb = (uint32_t)(tap * 16 + sh * 8) * 4u;

        uint32_t AH[2][4], AL[2][4];
#pragma unroll
        for (int mt = 0; mt < 2; mt++) {
            uint32_t ad = aaddr[mt][tap] + ka;
            LDSM_X4(AH[mt], ad);
            LDSM_X4(AL[mt], ad + ALOFS);
        }
        uint32_t BH[2][4], BL[2][4];
#pragma unroll
        for (int p = 0; p < 2; p++) {
            uint32_t bd = baddr[p] + kb;
            LDSM_X4(BH[p], bd);
            LDSM_X4(BL[p], bd + BLOFS);
        }

#pragma unroll
        for (int nt = 0; nt < 4; nt++) {
            int p = nt >> 1, q2 = (nt & 1) * 2;
            uint32_t bh0 = BH[p][q2], bh1 = BH[p][q2 + 1];
            uint32_t bl0 = BL[p][q2], bl1 = BL[p][q2 + 1];
#pragma unroll
            for (int mt = 0; mt < 2; mt++) {
                MMA_BF16(acc[mt][nt], AH[mt][0], AH[mt][1], AH[mt][2], AH[mt][3], bh0, bh1);
                MMA_BF16(acc[mt][nt], AL[mt][0], AL[mt][1], AL[mt][2], AL[mt][3], bh0, bh1);
                MMA_BF16(acc[mt][nt], AH[mt][0], AH[mt][1], AH[mt][2], AH[mt][3], bl0, bl1);
            }
        }
    }

    // ---- epilogue: bias + relu ----
    const float* sbias = ((const float*)smu) + OFF_BI;
    if (mode & 4) {
        // pair output: per pixel [16 hi][16 lo] words
#pragma unroll
        for (int mt = 0; mt < 2; mt++) {
#pragma unroll
            for (int half = 0; half < 2; half++) {
                int pp = p0 + m_warp + mt * 16 + half * 8 + g;
                if (pp < NPIX) {
                    uint32_t* op = reinterpret_cast<uint32_t*>(outp)
                                   + (size_t)(b * NPIX + pp) * 32;
#pragma unroll
                    for (int nt = 0; nt < 4; nt++) {
                        int col = nt * 8 + tg * 2;
                        float vx = fmaxf(acc[mt][nt][half * 2 + 0] + sbias[col],     0.f);
                        float vy = fmaxf(acc[mt][nt][half * 2 + 1] + sbias[col + 1], 0.f);
                        uint32_t h = bf16x2_of(vx, vy);
                        float2 hf = bf16x2_to_f2(h);
                        uint32_t l = bf16x2_of(vx - hf.x, vy - hf.y);
                        op[col >> 1]        = h;
                        op[16 + (col >> 1)] = l;
                    }
                }
            }
        }
    } else {
        // fp32 output (final layer; consumed by seq_kernel)
#pragma unroll
        for (int mt = 0; mt < 2; mt++) {
#pragma unroll
            for (int half = 0; half < 2; half++) {
                int pp = p0 + m_warp + mt * 16 + half * 8 + g;
                if (pp < NPIX) {
                    float* op = outp + ((size_t)b * NPIX + pp) * 32;
#pragma unroll
                    for (int nt = 0; nt < 4; nt++) {
                        int col = nt * 8 + tg * 2;
                        float2 v;
                        v.x = fmaxf(acc[mt][nt][half * 2 + 0] + sbias[col],     0.f);
                        v.y = fmaxf(acc[mt][nt][half * 2 + 1] + sbias[col + 1], 0.f);
                        *reinterpret_cast<float2*>(op + col) = v;
                    }
                }
            }
        }
    }
}

// ---------------------------------------------------------------------------
// mlp_collapse: W(4x32) = w2(4x512) @ w1(512x32); wb = w2 @ b1 + b2.
// ---------------------------------------------------------------------------
__global__ void __launch_bounds__(128) mlp_collapse_kernel(
    const float* __restrict__ w1, const float* __restrict__ b1,
    const float* __restrict__ w2, const float* __restrict__ b2) {
    int tid = threadIdx.x;
    int o = tid >> 5, i = tid & 31;
    const float* w2r = w2 + o * 512;
    float s = 0.f;
#pragma unroll 8
    for (int k = 0; k < 512; k++) s += w2r[k] * w1[k * 32 + i];
    g_W[tid] = s;
    if (tid < 4) {
        const float* wr = w2 + tid * 512;
        float sb = 0.f;
#pragma unroll 8
        for (int k = 0; k < 512; k++) sb += wr[k] * b1[k];
        g_wb[tid] = sb + b2[tid];
    }
}

// ---------------------------------------------------------------------------
// seq: warp-per-batch-row GRU encoder + autoregressive decoder.
// R16: ALL recurrent weight matrices stored TRANSPOSED in smem
// (Wt[k][row], row-contiguous) -> scalar LDS, bank = lane id, conflict-free.
// The old row-major stride-36 float4 loads were 4-way bank-conflicted on
// every access. Accumulation order unchanged -> bit-identical results.
// ---------------------------------------------------------------------------
#define FULLM 0xffffffffu
__device__ __forceinline__ float sigmoidf_(float v) { return 1.f / (1.f + expf(-v)); }
__device__ __forceinline__ float softplusf_(float v) {
    return fmaxf(v, 0.f) + log1pf(expf(-fabsf(v)));
}

__global__ void __launch_bounds__(32) seq_kernel(
    const float* __restrict__ z,    const float* __restrict__ past,
    const float* __restrict__ ewih, const float* __restrict__ ewhh,
    const float* __restrict__ ebih, const float* __restrict__ ebhh,
    const float* __restrict__ dwih, const float* __restrict__ dwhh,
    const float* __restrict__ dbih, const float* __restrict__ dbhh,
    float* __restrict__ out) {
    int b = blockIdx.x, i = threadIdx.x;

    __shared__ float s_ehT[32 * 96];   // ewhh^T: [k][row]
    __shared__ float s_dhT[32 * 96];   // dwhh^T: [k][row]
    __shared__ float s_diT[34 * 96];   // dwih^T: [c][row]
    __shared__ float s_eT[2 * 96];     // ewih^T: [c][row]
    __shared__ float s_ebih[96], s_ebhh[96], s_dbih[96], s_dbhh[96];
    __shared__ float s_W[128], s_wb[4];

    for (int u = i; u < 3072; u += 32) {
        int r = u >> 5, k = u & 31;
        s_ehT[k * 96 + r] = ewhh[u];
        s_dhT[k * 96 + r] = dwhh[u];
    }
    for (int u = i; u < 96 * 34; u += 32) {
        int r = u / 34, c = u % 34;
        s_diT[c * 96 + r] = dwih[u];
    }
    for (int u = i; u < 192; u += 32) {
        int r = u >> 1, c = u & 1;
        s_eT[c * 96 + r] = ewih[u];
    }
    for (int u = i; u < 96; u += 32) {
        s_ebih[u] = ebih[u]; s_ebhh[u] = ebhh[u];
        s_dbih[u] = dbih[u]; s_dbhh[u] = dbhh[u];
    }
    for (int u = i; u < 128; u += 32) s_W[u] = g_W[u];
    if (i < 4) s_wb[i] = g_wb[i];
    __syncwarp();

    float hi = 0.f;
    float harr[32];
#pragma unroll
    for (int k = 0; k < 32; k++) harr[k] = 0.f;

    // ---- encoder ----
    const float* pb = past + (size_t)b * TPAST * 2;
    for (int t = 0; t < TPAST; t++) {
        float x0 = pb[2 * t], x1 = pb[2 * t + 1];
        float g0 = s_ebih[i]      + x0 * s_eT[i]      + x1 * s_eT[96 + i];
        float g1 = s_ebih[32 + i] + x0 * s_eT[32 + i] + x1 * s_eT[96 + 32 + i];
        float g2 = s_ebih[64 + i] + x0 * s_eT[64 + i] + x1 * s_eT[96 + 64 + i];
        float h0 = s_ebhh[i], h1 = s_ebhh[32 + i], h2 = s_ebhh[64 + i];
#pragma unroll
        for (int k = 0; k < 32; k++) {
            float hk = harr[k];
            const float* wp = &s_ehT[k * 96 + i];
            h0 += hk * wp[0];
            h1 += hk * wp[32];
            h2 += hk * wp[64];
        }
        float rg = sigmoidf_(g0 + h0);
        float zg = sigmoidf_(g1 + h1);
        float nn = tanhf(g2 + rg * h2);
        hi = (1.f - zg) * nn + zg * hi;
#pragma unroll
        for (int k = 0; k < 32; k++) harr[k] = __shfl_sync(FULLM, hi, k);
    }

    float y1x = pb[2 * 19], y1y = pb[2 * 19 + 1];
    float y2x = pb[2 * 18], y2y = pb[2 * 18 + 1];
    float prod0 = 1.f, prod1 = 1.f;
    const float* ctx = g_bufB + (size_t)b * NPIX * 32;
    const float* zb = z + (size_t)b * TFUT * 2;

    // ---- decoder ----
    for (int t = 0; t < TFUT; t++) {
        float fyf = fminf(fmaxf(floorf(y1x), 0.f), (float)(GHH - 2));
        float fxf = fminf(fmaxf(floorf(y1y), 0.f), (float)(GWW - 2));
        float ay = fminf(fmaxf(y1x - fyf, 0.f), 1.f);
        float ax = fminf(fmaxf(y1y - fxf, 0.f), 1.f);
        int fy = (int)fyf, fx = (int)fxf;
        const float* gb = ctx + ((size_t)fy * GWW + fx) * 32 + i;
        float tl = gb[0], tr = gb[32], bl = gb[GWW * 32], br = gb[GWW * 32 + 32];
        float top = tl + ax * (tr - tl);
        float bot = bl + ax * (br - bl);
        float xi = top + ay * (bot - top);
        float xarr[32];
#pragma unroll
        for (int k = 0; k < 32; k++) xarr[k] = __shfl_sync(FULLM, xi, k);

        float g0 = s_dbih[i]      + y1x * s_diT[i]      + y1y * s_diT[96 + i];
        float g1 = s_dbih[32 + i] + y1x * s_diT[32 + i] + y1y * s_diT[96 + 32 + i];
        float g2 = s_dbih[64 + i] + y1x * s_diT[64 + i] + y1y * s_diT[96 + 64 + i];
        float h0 = s_dbhh[i], h1 = s_dbhh[32 + i], h2 = s_dbhh[64 + i];
#pragma unroll
        for (int k = 0; k < 32; k++) {
            float xk = xarr[k];
            const float* ip = &s_diT[(k + 2) * 96 + i];
            g0 += xk * ip[0];
            g1 += xk * ip[32];
            g2 += xk * ip[64];
            float hk = harr[k];
            const float* wp = &s_dhT[k * 96 + i];
            h0 += hk * wp[0];
            h1 += hk * wp[32];
            h2 += hk * wp[64];
        }
        float rg = sigmoidf_(g0 + h0);
        float zg = sigmoidf_(g1 + h1);
        float nn = tanhf(g2 + rg * h2);
        hi = (1.f - zg) * nn + zg * hi;
#pragma unroll
        for (int k = 0; k < 32; k++) harr[k] = __shfl_sync(FULLM, hi, k);

        float p0 = s_W[i] * hi;
        float p1 = s_W[32 + i] * hi;
        float p2 = s_W[64 + i] * hi;
        float p3 = s_W[96 + i] * hi;
#pragma unroll
        for (int off = 16; off; off >>= 1) {
            p0 += __shfl_xor_sync(FULLM, p0, off);
            p1 += __shfl_xor_sync(FULLM, p1, off);
            p2 += __shfl_xor_sync(FULLM, p2, off);
            p3 += __shfl_xor_sync(FULLM, p3, off);
        }
        float loc0 = p0 + s_wb[0], loc1 = p1 + s_wb[1];
        float s0 = softplusf_(p2 + s_wb[2]);
        float s1 = softplusf_(p3 + s_wb[3]);
        float zt0 = zb[2 * t], zt1 = zb[2 * t + 1];
        float ynx = 2.f * y1x - y2x + loc0 + s0 * zt0;
        float yny = 2.f * y1y - y2y + loc1 + s1 * zt1;
        if (i == 0) {
            out[((size_t)b * TFUT + t) * 2]     = ynx;
            out[((size_t)b * TFUT + t) * 2 + 1] = yny;
        }
        prod0 *= s0; prod1 *= s1;
        y2x = y1x; y2y = y1y;
        y1x = ynx; y1y = yny;
    }
    if (i == 0)
        out[(size_t)BATCH * TFUT * 2 + b] = logf(fabsf(prod0)) + logf(fabsf(prod1));
}

// ---------------------------------------------------------------------------
extern "C" void kernel_launch(void* const* d_in, const int* in_sizes, int n_in,
                              void* d_out, int out_size) {
    const float* z    = (const float*)d_in[0];
    const float* past = (const float*)d_in[1];
    const float* lidar= (const float*)d_in[2];
    const float* c0w  = (const float*)d_in[3];
    const float* c0b  = (const float*)d_in[4];
    const float* c1w  = (const float*)d_in[5];
    const float* c1b  = (const float*)d_in[6];
    const float* c2w  = (const float*)d_in[7];
    const float* c2b  = (const float*)d_in[8];
    const float* c3w  = (const float*)d_in[9];
    const float* c3b  = (const float*)d_in[10];
    const float* ewih = (const float*)d_in[11];
    const float* ewhh = (const float*)d_in[12];
    const float* ebih = (const float*)d_in[13];
    const float* ebhh = (const float*)d_in[14];
    const float* dwih = (const float*)d_in[15];
    const float* dwhh = (const float*)d_in[16];
    const float* dbih = (const float*)d_in[17];
    const float* dbhh = (const float*)d_in[18];
    const float* w1   = (const float*)d_in[19];
    const float* b1   = (const float*)d_in[20];
    const float* w2   = (const float*)d_in[21];
    const float* b2   = (const float*)d_in[22];
    float* out = (float*)d_out;

    cudaFuncSetAttribute(convF_kernel, cudaFuncAttributeMaxDynamicSharedMemorySize,
                         CM_SMEM);

    mlp_collapse_kernel<<<1, 128>>>(w1, b1, w2, b2);

    dim3 cg((NPIX + PIXB - 1) / PIXB, BATCH);
    // layer 1: conv0 fused, pair output          -> g_bufB (pairs)
    convF_kernel<<<cg, NTHR, CM_SMEM>>>(c1w, c1b, c0w, c0b, lidar, 1, 1 | 4);
    // layer 2: pair input, pair output           g_bufB -> g_bufA (pairs)
    convF_kernel<<<cg, NTHR, CM_SMEM>>>(c2w, c2b, c0w, c0b, lidar, 0, 2 | 4);
    // layer 3: pair input, fp32 output           g_bufA -> g_bufB (fp32 ctx)
    convF_kernel<<<cg, NTHR, CM_SMEM>>>(c3w, c3b, c0w, c0b, lidar, 1, 2);

    seq_kernel<<<BATCH, 32>>>(z, past, ewih, ewhh, ebih, ebhh,
                              dwih, dwhh, dbih, dbhh, out);
}

// round 17
// speedup vs baseline: 1.1421x; 1.0736x over previous
#include <cuda_runtime.h>
#include <math.h>
#include <stdint.h>

#define BATCH 256
#define GHH 100
#define GWW 100
#define CH 32
#define TPAST 20
#define TFUT 30
#define NPIX (GHH * GWW)

// Ping-pong scratch for the conv stack (sanctioned __device__ global scratch).
// Pair layout (intermediate layers): per pixel 32 words = [16 hi][16 lo] bf16x2.
__device__ __align__(128) float g_bufA[(size_t)BATCH*NPIX*CH];
__device__ __align__(128) float g_bufB[(size_t)BATCH*NPIX*CH];
// Collapsed MLP: W = mlp_w2 @ mlp_w1 (4x32), wb = mlp_w2 @ mlp_b1 + mlp_b2.
__device__ float g_W[128];
__device__ float g_wb[4];
// Encoder output hidden state (per batch row).
__device__ float g_henc[BATCH * 32];

// ---------------------------------------------------------------------------
// convF: 2x2 conv (32ch->32ch) as warp-level mma.sync bf16 m16n8k16 GEMM with
// 3-term compensation (D = Ah*Bh + Al*Bh + Ah*Bl).  (R14 config — best.)
// mode bits: 1 = fuse conv0 (layer 1), 2 = pair input, 4 = pair output.
// ---------------------------------------------------------------------------
#define PIXB 224
#define NTHR 224
#define APITCH 20
#define BPITCH 68
#define NSTRIP 326
#define ZROW 325
#define NLID 427
#define OFF_AH 0
#define OFF_AL (NSTRIP * APITCH)
#define OFF_BH (2 * NSTRIP * APITCH)
#define OFF_BL (OFF_BH + 32 * BPITCH)
#define OFF_BI (OFF_BL + 32 * BPITCH)
#define OFF_LID (OFF_BI + 32)
#define CM_WORDS (OFF_LID + NLID * 2 + 2)
#define CM_SMEM (CM_WORDS * 4)
#define ALOFS ((OFF_AL - OFF_AH) * 4)
#define BLOFS ((OFF_BL - OFF_BH) * 4)

#define MMA_BF16(C, A0, A1, A2, A3, B0, B1)                                  \
    asm volatile("mma.sync.aligned.m16n8k16.row.col.f32.bf16.bf16.f32 "      \
                 "{%0,%1,%2,%3}, {%4,%5,%6,%7}, {%8,%9}, {%0,%1,%2,%3};"     \
                 : "+f"(C[0]), "+f"(C[1]), "+f"(C[2]), "+f"(C[3])            \
                 : "r"(A0), "r"(A1), "r"(A2), "r"(A3), "r"(B0), "r"(B1))

#define LDSM_X4(R, addr)                                                     \
    asm volatile("ldmatrix.sync.aligned.m8n8.x4.shared.b16 "                 \
                 "{%0,%1,%2,%3}, [%4];"                                      \
                 : "=r"((R)[0]), "=r"((R)[1]), "=r"((R)[2]), "=r"((R)[3])    \
                 : "r"(addr))

__device__ __forceinline__ uint32_t bf16x2_of(float lo, float hi) {
    uint32_t r;
    asm("cvt.rn.bf16x2.f32 %0, %1, %2;" : "=r"(r) : "f"(hi), "f"(lo));
    return r;
}
__device__ __forceinline__ float2 bf16x2_to_f2(uint32_t u) {
    float2 r;
    r.x = __uint_as_float(u << 16);
    r.y = __uint_as_float(u & 0xFFFF0000u);
    return r;
}

__global__ void __launch_bounds__(NTHR, 3) convF_kernel(
    const float* __restrict__ w,  const float* __restrict__ bias,
    const float* __restrict__ w0, const float* __restrict__ b0,
    const float* __restrict__ lidar, int srcIsA, int mode) {
    extern __shared__ uint32_t smu[];
    const float* in   = srcIsA ? g_bufA : g_bufB;
    float*       outp = srcIsA ? g_bufB : g_bufA;

    int tid = threadIdx.x;
    int b   = blockIdx.y;
    int p0  = blockIdx.x * PIXB;
    uint32_t sbase = (uint32_t)__cvta_generic_to_shared(smu);

    // ---- phase 1: issue async gmem->smem copies FIRST ----
    if (mode & 1) {
        const float* lb = lidar + (size_t)b * NPIX * 2;
        for (int i = tid; i < NLID; i += NTHR) {
            int gp = p0 + i;
            uint32_t daddr = sbase + (uint32_t)(OFF_LID + 2 * i) * 4u;
            if (gp < NPIX) {
                asm volatile("cp.async.ca.shared.global [%0], [%1], 8;"
                             :: "r"(daddr), "l"(lb + (size_t)gp * 2));
            } else {
                smu[OFF_LID + 2 * i]     = 0u;
                smu[OFF_LID + 2 * i + 1] = 0u;
            }
        }
    } else {
        const uint4* src = reinterpret_cast<const uint4*>(in) + (size_t)b * NPIX * 8;
        for (int i = tid; i < NSTRIP * 8; i += NTHR) {
            int pix = i >> 3, c = i & 7;
            int gp = p0 + pix;
            uint32_t dw = (uint32_t)(((c >> 2) ? OFF_AL : OFF_AH)
                                     + pix * APITCH + (c & 3) * 4);
            if (pix < ZROW && gp < NPIX) {
                const uint4* gsrc = src + (size_t)gp * 8 + c;
                asm volatile("cp.async.cg.shared.global [%0], [%1], 16;"
                             :: "r"(sbase + dw * 4u), "l"(gsrc));
            } else {
                *reinterpret_cast<uint4*>(&smu[dw]) = make_uint4(0u, 0u, 0u, 0u);
            }
        }
    }
    asm volatile("cp.async.commit_group;" ::: "memory");

    // ---- phase 2 (overlapped): weights -> bf16x2 hi/lo pairs ----
    for (int i = tid; i < 2048; i += NTHR) {
        int n = i & 31, j = i >> 5;
        float v0 = w[(2 * j) * 32 + n];
        float v1 = w[(2 * j + 1) * 32 + n];
        uint32_t h = bf16x2_of(v0, v1);
        float2 hf = bf16x2_to_f2(h);
        uint32_t l = bf16x2_of(v0 - hf.x, v1 - hf.y);
        smu[OFF_BH + n * BPITCH + j] = h;
        smu[OFF_BL + n * BPITCH + j] = l;
    }
    if (tid < 32) ((float*)smu)[OFF_BI + tid] = bias[tid];

    asm volatile("cp.async.wait_group 0;" ::: "memory");
    __syncthreads();

    if (mode & 1) {
        int sub = tid & 7;
        float wc[8][4], bc[4];
#pragma unroll
        for (int q = 0; q < 4; q++) bc[q] = b0[sub * 4 + q];
#pragma unroll
        for (int k = 0; k < 8; k++)
#pragma unroll
            for (int q = 0; q < 4; q++) wc[k][q] = w0[k * 32 + sub * 4 + q];

        const float* sl = (const float*)&smu[OFF_LID];
        for (int u = tid; u < NSTRIP * 8; u += NTHR) {
            int pix = u >> 3;
            int gp = p0 + pix;
            uint32_t h0 = 0, h1 = 0, l0 = 0, l1 = 0;
            if (pix < ZROW && gp < NPIX) {
                int y = gp / GWW, x = gp % GWW;
                bool xe = (x == GWW - 1), ye = (y == GHH - 1);
                float a[8];
#pragma unroll
                for (int dy = 0; dy < 2; dy++)
#pragma unroll
                    for (int dx = 0; dx < 2; dx++) {
                        bool ok = !(dy && ye) && !(dx && xe);
                        const float* ip = sl + (pix + dy * GWW + dx) * 2;
                        a[(dy * 2 + dx) * 2 + 0] = ok ? ip[0] : 0.f;
                        a[(dy * 2 + dx) * 2 + 1] = ok ? ip[1] : 0.f;
                    }
                float v[4];
#pragma unroll
                for (int q = 0; q < 4; q++) {
                    float s = bc[q];
#pragma unroll
                    for (int k = 0; k < 8; k++) s += a[k] * wc[k][q];
                    v[q] = fmaxf(s, 0.f);
                }
                h0 = bf16x2_of(v[0], v[1]);
                h1 = bf16x2_of(v[2], v[3]);
                float2 f0 = bf16x2_to_f2(h0), f1 = bf16x2_to_f2(h1);
                l0 = bf16x2_of(v[0] - f0.x, v[1] - f0.y);
                l1 = bf16x2_of(v[2] - f1.x, v[3] - f1.y);
            }
            int j = sub * 2;
            smu[OFF_AH + pix * APITCH + j]     = h0;
            smu[OFF_AH + pix * APITCH + j + 1] = h1;
            smu[OFF_AL + pix * APITCH + j]     = l0;
            smu[OFF_AL + pix * APITCH + j + 1] = l1;
        }
        __syncthreads();
    }

    int lane = tid & 31, wid = tid >> 5;
    int g = lane >> 2, tg = lane & 3;
    int m_warp = wid * 32;

    int row16  = ((lane >> 3) & 1) * 8 + (lane & 7);
    int khalfA = (lane >> 4) & 1;
    uint32_t aaddr[2][4];
#pragma unroll
    for (int mt = 0; mt < 2; mt++) {
        int pix = m_warp + mt * 16 + row16;
        bool wrap = (((p0 + pix) % GWW) == (GWW - 1));
#pragma unroll
        for (int tap = 0; tap < 4; tap++) {
            int rr = pix + (tap >> 1) * GWW + (tap & 1);
            int rowpix = ((tap & 1) && wrap) ? ZROW : rr;
            aaddr[mt][tap] = sbase + (uint32_t)(rowpix * APITCH + khalfA * 4) * 4u;
        }
    }
    int ntp  = (lane >> 4) & 1;
    int matk = (lane >> 3) & 1;
    int nrow = lane & 7;
    uint32_t baddr[2];
#pragma unroll
    for (int p = 0; p < 2; p++)
        baddr[p] = sbase + (uint32_t)(OFF_BH + ((2 * p + ntp) * 8 + nrow) * BPITCH
                                      + matk * 4) * 4u;

    float acc[2][4][4];
#pragma unroll
    for (int mt = 0; mt < 2; mt++)
#pragma unroll
        for (int nt = 0; nt < 4; nt++)
#pragma unroll
            for (int q = 0; q < 4; q++) acc[mt][nt][q] = 0.f;

#pragma unroll
    for (int s = 0; s < 8; s++) {
        int tap = s >> 1, sh = s & 1;
        uint32_t ka = (uint32_t)(sh * 8) * 4u;
        uint32_t kb = (uint32_t)(tap * 16 + sh * 8) * 4u;

        uint32_t AH[2][4], AL[2][4];
#pragma unroll
        for (int mt = 0; mt < 2; mt++) {
            uint32_t ad = aaddr[mt][tap] + ka;
            LDSM_X4(AH[mt], ad);
            LDSM_X4(AL[mt], ad + ALOFS);
        }
        uint32_t BH[2][4], BL[2][4];
#pragma unroll
        for (int p = 0; p < 2; p++) {
            uint32_t bd = baddr[p] + kb;
            LDSM_X4(BH[p], bd);
            LDSM_X4(BL[p], bd + BLOFS);
        }

#pragma unroll
        for (int nt = 0; nt < 4; nt++) {
            int p = nt >> 1, q2 = (nt & 1) * 2;
            uint32_t bh0 = BH[p][q2], bh1 = BH[p][q2 + 1];
            uint32_t bl0 = BL[p][q2], bl1 = BL[p][q2 + 1];
#pragma unroll
            for (int mt = 0; mt < 2; mt++) {
                MMA_BF16(acc[mt][nt], AH[mt][0], AH[mt][1], AH[mt][2], AH[mt][3], bh0, bh1);
                MMA_BF16(acc[mt][nt], AL[mt][0], AL[mt][1], AL[mt][2], AL[mt][3], bh0, bh1);
                MMA_BF16(acc[mt][nt], AH[mt][0], AH[mt][1], AH[mt][2], AH[mt][3], bl0, bl1);
            }
        }
    }

    const float* sbias = ((const float*)smu) + OFF_BI;
    if (mode & 4) {
#pragma unroll
        for (int mt = 0; mt < 2; mt++) {
#pragma unroll
            for (int half = 0; half < 2; half++) {
                int pp = p0 + m_warp + mt * 16 + half * 8 + g;
                if (pp < NPIX) {
                    uint32_t* op = reinterpret_cast<uint32_t*>(outp)
                                   + (size_t)(b * NPIX + pp) * 32;
#pragma unroll
                    for (int nt = 0; nt < 4; nt++) {
                        int col = nt * 8 + tg * 2;
                        float vx = fmaxf(acc[mt][nt][half * 2 + 0] + sbias[col],     0.f);
                        float vy = fmaxf(acc[mt][nt][half * 2 + 1] + sbias[col + 1], 0.f);
                        uint32_t h = bf16x2_of(vx, vy);
                        float2 hf = bf16x2_to_f2(h);
                        uint32_t l = bf16x2_of(vx - hf.x, vy - hf.y);
                        op[col >> 1]        = h;
                        op[16 + (col >> 1)] = l;
                    }
                }
            }
        }
    } else {
#pragma unroll
        for (int mt = 0; mt < 2; mt++) {
#pragma unroll
            for (int half = 0; half < 2; half++) {
                int pp = p0 + m_warp + mt * 16 + half * 8 + g;
                if (pp < NPIX) {
                    float* op = outp + ((size_t)b * NPIX + pp) * 32;
#pragma unroll
                    for (int nt = 0; nt < 4; nt++) {
                        int col = nt * 8 + tg * 2;
                        float2 v;
                        v.x = fmaxf(acc[mt][nt][half * 2 + 0] + sbias[col],     0.f);
                        v.y = fmaxf(acc[mt][nt][half * 2 + 1] + sbias[col + 1], 0.f);
                        *reinterpret_cast<float2*>(op + col) = v;
                    }
                }
            }
        }
    }
}

// ---------------------------------------------------------------------------
// mlp_collapse: W(4x32) = w2(4x512) @ w1(512x32); wb = w2 @ b1 + b2.
// ---------------------------------------------------------------------------
__global__ void __launch_bounds__(128) mlp_collapse_kernel(
    const float* __restrict__ w1, const float* __restrict__ b1,
    const float* __restrict__ w2, const float* __restrict__ b2) {
    int tid = threadIdx.x;
    int o = tid >> 5, i = tid & 31;
    const float* w2r = w2 + o * 512;
    float s = 0.f;
#pragma unroll 8
    for (int k = 0; k < 512; k++) s += w2r[k] * w1[k * 32 + i];
    g_W[tid] = s;
    if (tid < 4) {
        const float* wr = w2 + tid * 512;
        float sb = 0.f;
#pragma unroll 8
        for (int k = 0; k < 512; k++) sb += wr[k] * b1[k];
        g_wb[tid] = sb + b2[tid];
    }
}

#define FULLM 0xffffffffu
__device__ __forceinline__ float sigmoidf_(float v) { return 1.f / (1.f + expf(-v)); }
__device__ __forceinline__ float softplusf_(float v) {
    return fmaxf(v, 0.f) + log1pf(expf(-fabsf(v)));
}

// ---------------------------------------------------------------------------
// enc: encoder GRU (20 steps), warp per batch row. Independent of the convs —
// runs on the side stream, overlapped with the conv stack. Writes g_henc.
// ---------------------------------------------------------------------------
__global__ void __launch_bounds__(32) enc_kernel(
    const float* __restrict__ past,
    const float* __restrict__ ewih, const float* __restrict__ ewhh,
    const float* __restrict__ ebih, const float* __restrict__ ebhh) {
    int b = blockIdx.x, i = threadIdx.x;
    __shared__ __align__(16) float s_ewhh[96 * 36];
    __shared__ float s_eih[192];
    __shared__ float s_ebih[96], s_ebhh[96];

    for (int u = i; u < 3072; u += 32) {
        int r = u >> 5, c = u & 31;
        s_ewhh[r * 36 + c] = ewhh[u];
    }
    for (int u = i; u < 192; u += 32) s_eih[u] = ewih[u];
    for (int u = i; u < 96; u += 32) { s_ebih[u] = ebih[u]; s_ebhh[u] = ebhh[u]; }
    __syncwarp();

    float hi = 0.f;
    float harr[32];
#pragma unroll
    for (int k = 0; k < 32; k++) harr[k] = 0.f;

    const float* pb = past + (size_t)b * TPAST * 2;
    for (int t = 0; t < TPAST; t++) {
        float x0 = pb[2 * t], x1 = pb[2 * t + 1];
        float g0 = s_ebih[i]      + x0 * s_eih[2 * i]            + x1 * s_eih[2 * i + 1];
        float g1 = s_ebih[32 + i] + x0 * s_eih[2 * (32 + i)]     + x1 * s_eih[2 * (32 + i) + 1];
        float g2 = s_ebih[64 + i] + x0 * s_eih[2 * (64 + i)]     + x1 * s_eih[2 * (64 + i) + 1];
        float h0 = s_ebhh[i], h1 = s_ebhh[32 + i], h2 = s_ebhh[64 + i];
        const float4* w0p = (const float4*)&s_ewhh[i * 36];
        const float4* w1p = (const float4*)&s_ewhh[(32 + i) * 36];
        const float4* w2p = (const float4*)&s_ewhh[(64 + i) * 36];
#pragma unroll
        for (int q = 0; q < 8; q++) {
            float4 a0 = w0p[q], a1 = w1p[q], a2 = w2p[q];
            float k0 = harr[4 * q], k1 = harr[4 * q + 1], k2 = harr[4 * q + 2], k3 = harr[4 * q + 3];
            h0 += k0 * a0.x + k1 * a0.y + k2 * a0.z + k3 * a0.w;
            h1 += k0 * a1.x + k1 * a1.y + k2 * a1.z + k3 * a1.w;
            h2 += k0 * a2.x + k1 * a2.y + k2 * a2.z + k3 * a2.w;
        }
        float rg = sigmoidf_(g0 + h0);
        float zg = sigmoidf_(g1 + h1);
        float nn = tanhf(g2 + rg * h2);
        hi = (1.f - zg) * nn + zg * hi;
#pragma unroll
        for (int k = 0; k < 32; k++) harr[k] = __shfl_sync(FULLM, hi, k);
    }
    g_henc[b * 32 + i] = hi;
}

// ---------------------------------------------------------------------------
// dec: autoregressive decoder (30 steps), warp per batch row. h-matvec hoisted
// ahead of the bilinear-dependent work to overlap the gather latency.
// ---------------------------------------------------------------------------
__global__ void __launch_bounds__(32) dec_kernel(
    const float* __restrict__ z,    const float* __restrict__ past,
    const float* __restrict__ dwih, const float* __restrict__ dwhh,
    const float* __restrict__ dbih, const float* __restrict__ dbhh,
    float* __restrict__ out) {
    int b = blockIdx.x, i = threadIdx.x;
    __shared__ __align__(16) float s_dwhh[96 * 36];
    __shared__ __align__(16) float s_dwih[96 * 36];   // [0,1]=y1 wts, [4..35]=interp wts
    __shared__ float s_dbih[96], s_dbhh[96];
    __shared__ float s_W[128], s_wb[4];

    for (int u = i; u < 3072; u += 32) {
        int r = u >> 5, c = u & 31;
        s_dwhh[r * 36 + c] = dwhh[u];
    }
    for (int u = i; u < 96 * 34; u += 32) {
        int r = u / 34, c = u % 34;
        s_dwih[r * 36 + (c < 2 ? c : c + 2)] = dwih[u];
    }
    for (int u = i; u < 96; u += 32) { s_dbih[u] = dbih[u]; s_dbhh[u] = dbhh[u]; }
    for (int u = i; u < 128; u += 32) s_W[u] = g_W[u];
    if (i < 4) s_wb[i] = g_wb[i];
    __syncwarp();

    float hi = g_henc[b * 32 + i];
    float harr[32];
#pragma unroll
    for (int k = 0; k < 32; k++) harr[k] = __shfl_sync(FULLM, hi, k);

    const float* pb = past + (size_t)b * TPAST * 2;
    float y1x = pb[2 * 19], y1y = pb[2 * 19 + 1];
    float y2x = pb[2 * 18], y2y = pb[2 * 18 + 1];
    float prod0 = 1.f, prod1 = 1.f;
    const float* ctx = g_bufB + (size_t)b * NPIX * 32;
    const float* zb = z + (size_t)b * TFUT * 2;

    for (int t = 0; t < TFUT; t++) {
        // issue the bilinear gather first (data-dependent DRAM latency)
        float fyf = fminf(fmaxf(floorf(y1x), 0.f), (float)(GHH - 2));
        float fxf = fminf(fmaxf(floorf(y1y), 0.f), (float)(GWW - 2));
        float ay = fminf(fmaxf(y1x - fyf, 0.f), 1.f);
        float ax = fminf(fmaxf(y1y - fxf, 0.f), 1.f);
        int fy = (int)fyf, fx = (int)fxf;
        const float* gb = ctx + ((size_t)fy * GWW + fx) * 32 + i;
        float tl = gb[0], tr = gb[32], bl = gb[GWW * 32], br = gb[GWW * 32 + 32];

        // h-part matvec (independent of the gather) overlaps the load latency
        float h0 = s_dbhh[i], h1 = s_dbhh[32 + i], h2 = s_dbhh[64 + i];
        {
            const float4* w0p = (const float4*)&s_dwhh[i * 36];
            const float4* w1p = (const float4*)&s_dwhh[(32 + i) * 36];
            const float4* w2p = (const float4*)&s_dwhh[(64 + i) * 36];
#pragma unroll
            for (int q = 0; q < 8; q++) {
                float4 c0 = w0p[q], c1 = w1p[q], c2 = w2p[q];
                float m0 = harr[4 * q], m1 = harr[4 * q + 1], m2 = harr[4 * q + 2], m3 = harr[4 * q + 3];
                h0 += m0 * c0.x + m1 * c0.y + m2 * c0.z + m3 * c0.w;
                h1 += m0 * c1.x + m1 * c1.y + m2 * c1.z + m3 * c1.w;
                h2 += m0 * c2.x + m1 * c2.y + m2 * c2.z + m3 * c2.w;
            }
        }

        // combine bilinear and broadcast
        float top = tl + ax * (tr - tl);
        float bot = bl + ax * (br - bl);
        float xi = top + ay * (bot - top);
        float xarr[32];
#pragma unroll
        for (int k = 0; k < 32; k++) xarr[k] = __shfl_sync(FULLM, xi, k);

        // g-part matvec
        float g0 = s_dbih[i]      + y1x * s_dwih[i * 36]            + y1y * s_dwih[i * 36 + 1];
        float g1 = s_dbih[32 + i] + y1x * s_dwih[(32 + i) * 36]     + y1y * s_dwih[(32 + i) * 36 + 1];
        float g2 = s_dbih[64 + i] + y1x * s_dwih[(64 + i) * 36]     + y1y * s_dwih[(64 + i) * 36 + 1];
        {
            const float4* xi0 = (const float4*)&s_dwih[i * 36 + 4];
            const float4* xi1 = (const float4*)&s_dwih[(32 + i) * 36 + 4];
            const float4* xi2 = (const float4*)&s_dwih[(64 + i) * 36 + 4];
#pragma unroll
            for (int q = 0; q < 8; q++) {
                float4 a0 = xi0[q], a1 = xi1[q], a2 = xi2[q];
                float k0 = xarr[4 * q], k1 = xarr[4 * q + 1], k2 = xarr[4 * q + 2], k3 = xarr[4 * q + 3];
                g0 += k0 * a0.x + k1 * a0.y + k2 * a0.z + k3 * a0.w;
                g1 += k0 * a1.x + k1 * a1.y + k2 * a1.z + k3 * a1.w;
                g2 += k0 * a2.x + k1 * a2.y + k2 * a2.z + k3 * a2.w;
            }
        }
        float rg = sigmoidf_(g0 + h0);
        float zg = sigmoidf_(g1 + h1);
        float nn = tanhf(g2 + rg * h2);
        hi = (1.f - zg) * nn + zg * hi;
#pragma unroll
        for (int k = 0; k < 32; k++) harr[k] = __shfl_sync(FULLM, hi, k);

        float p0 = s_W[i] * hi;
        float p1 = s_W[32 + i] * hi;
        float p2 = s_W[64 + i] * hi;
        float p3 = s_W[96 + i] * hi;
#pragma unroll
        for (int off = 16; off; off >>= 1) {
            p0 += __shfl_xor_sync(FULLM, p0, off);
            p1 += __shfl_xor_sync(FULLM, p1, off);
            p2 += __shfl_xor_sync(FULLM, p2, off);
            p3 += __shfl_xor_sync(FULLM, p3, off);
        }
        float loc0 = p0 + s_wb[0], loc1 = p1 + s_wb[1];
        float s0 = softplusf_(p2 + s_wb[2]);
        float s1 = softplusf_(p3 + s_wb[3]);
        float zt0 = zb[2 * t], zt1 = zb[2 * t + 1];
        float ynx = 2.f * y1x - y2x + loc0 + s0 * zt0;
        float yny = 2.f * y1y - y2y + loc1 + s1 * zt1;
        if (i == 0) {
            out[((size_t)b * TFUT + t) * 2]     = ynx;
            out[((size_t)b * TFUT + t) * 2 + 1] = yny;
        }
        prod0 *= s0; prod1 *= s1;
        y2x = y1x; y2y = y1y;
        y1x = ynx; y1y = yny;
    }
    if (i == 0)
        out[(size_t)BATCH * TFUT * 2 + b] = logf(fabsf(prod0)) + logf(fabsf(prod1));
}

// ---------------------------------------------------------------------------
extern "C" void kernel_launch(void* const* d_in, const int* in_sizes, int n_in,
                              void* d_out, int out_size) {
    const float* z    = (const float*)d_in[0];
    const float* past = (const float*)d_in[1];
    const float* lidar= (const float*)d_in[2];
    const float* c0w  = (const float*)d_in[3];
    const float* c0b  = (const float*)d_in[4];
    const float* c1w  = (const float*)d_in[5];
    const float* c1b  = (const float*)d_in[6];
    const float* c2w  = (const float*)d_in[7];
    const float* c2b  = (const float*)d_in[8];
    const float* c3w  = (const float*)d_in[9];
    const float* c3b  = (const float*)d_in[10];
    const float* ewih = (const float*)d_in[11];
    const float* ewhh = (const float*)d_in[12];
    const float* ebih = (const float*)d_in[13];
    const float* ebhh = (const float*)d_in[14];
    const float* dwih = (const float*)d_in[15];
    const float* dwhh = (const float*)d_in[16];
    const float* dbih = (const float*)d_in[17];
    const float* dbhh = (const float*)d_in[18];
    const float* w1   = (const float*)d_in[19];
    const float* b1   = (const float*)d_in[20];
    const float* w2   = (const float*)d_in[21];
    const float* b2   = (const float*)d_in[22];
    float* out = (float*)d_out;

    // Lazily created once on the first (non-captured) call; reused under
    // graph capture where the event record/wait become graph edges.
    static cudaStream_t s2 = nullptr;
    static cudaEvent_t evFork = nullptr, evJoin = nullptr;
    if (s2 == nullptr) {
        cudaStreamCreateWithFlags(&s2, cudaStreamNonBlocking);
        cudaEventCreateWithFlags(&evFork, cudaEventDisableTiming);
        cudaEventCreateWithFlags(&evJoin, cudaEventDisableTiming);
    }

    cudaFuncSetAttribute(convF_kernel, cudaFuncAttributeMaxDynamicSharedMemorySize,
                         CM_SMEM);

    // fork: mlp-collapse + encoder run concurrently with the conv stack
    cudaEventRecord(evFork, 0);
    cudaStreamWaitEvent(s2, evFork, 0);
    mlp_collapse_kernel<<<1, 128, 0, s2>>>(w1, b1, w2, b2);
    enc_kernel<<<BATCH, 32, 0, s2>>>(past, ewih, ewhh, ebih, ebhh);
    cudaEventRecord(evJoin, s2);

    dim3 cg((NPIX + PIXB - 1) / PIXB, BATCH);
    convF_kernel<<<cg, NTHR, CM_SMEM>>>(c1w, c1b, c0w, c0b, lidar, 1, 1 | 4);
    convF_kernel<<<cg, NTHR, CM_SMEM>>>(c2w, c2b, c0w, c0b, lidar, 0, 2 | 4);
    convF_kernel<<<cg, NTHR, CM_SMEM>>>(c3w, c3b, c0w, c0b, lidar, 1, 2);

    // join: decoder needs conv3 output + g_W + g_henc
    cudaStreamWaitEvent(0, evJoin, 0);
    dec_kernel<<<BATCH, 32>>>(z, past, dwih, dwhh, dbih, dbhh, out);
}